// round 4
// baseline (speedup 1.0000x reference)
#include <cuda_runtime.h>
#include <math.h>

#define NUM_ENT 40000
#define NUM_EMB 24
#define NUM_OPS 12
#define DIM     128
#define HID     128
#define BATCH   128
#define NNZ     300000
#define RANKS   3
#define STEPS   3
#define ETOT    (NUM_OPS * NNZ)
#define G4      (4 * HID)
#define NPART   200   // partial-reduction blocks (200 * 200 = 40000 rows)

// ---------------- scratch (device globals; no allocation allowed) ----------------
__device__ float4        g_memA[NUM_ENT * 32];        // (ENT, 128) as float4[ENT][32]
__device__ float4        g_memB[NUM_ENT * 32];
__device__ float         g_accum[NUM_ENT * BATCH];    // rank-accumulated, [j][b]
__device__ int           g_hist[NUM_ENT];
__device__ int           g_rowptr[NUM_ENT + 1];
__device__ int           g_cursor[NUM_ENT];
__device__ int           g_meta[ETOT];                // src | (op<<18)
__device__ float         g_eval[ETOT];
__device__ unsigned char g_flagA[NUM_ENT];
__device__ unsigned char g_flagB[NUM_ENT];
__device__ float         g_hseq[RANKS * 2 * STEPS * BATCH * HID];
__device__ float         g_attn[RANKS * STEPS * 13 * BATCH];   // [r][t][k][b]
__device__ float         g_part[NPART * BATCH];
__device__ float         g_inv[BATCH];

// ---------------- helpers ----------------
__device__ __forceinline__ float warp_sum(float p) {
    p += __shfl_xor_sync(0xffffffffu, p, 16);
    p += __shfl_xor_sync(0xffffffffu, p, 8);
    p += __shfl_xor_sync(0xffffffffu, p, 4);
    p += __shfl_xor_sync(0xffffffffu, p, 2);
    p += __shfl_xor_sync(0xffffffffu, p, 1);
    return p;
}

// ---------------- CSR build ----------------
__global__ void zero_hist_kernel() {
    int i = blockIdx.x * blockDim.x + threadIdx.x;
    if (i < NUM_ENT) g_hist[i] = 0;
}

__global__ void hist_kernel(const int* __restrict__ edge_dst) {
    int i = blockIdx.x * blockDim.x + threadIdx.x;
    if (i < ETOT) atomicAdd(&g_hist[edge_dst[i]], 1);
}

__global__ void scan_kernel() {   // 1 block, 1024 threads
    __shared__ int spart[1024];
    int tid = threadIdx.x;
    const int CH = (NUM_ENT + 1023) / 1024;  // 40
    int start = tid * CH;
    int s = 0;
    for (int k = 0; k < CH; k++) {
        int idx = start + k;
        if (idx < NUM_ENT) s += g_hist[idx];
    }
    spart[tid] = s;
    __syncthreads();
    if (tid == 0) {
        int run = 0;
        for (int i = 0; i < 1024; i++) { int v = spart[i]; spart[i] = run; run += v; }
        g_rowptr[NUM_ENT] = run;
    }
    __syncthreads();
    int run = spart[tid];
    for (int k = 0; k < CH; k++) {
        int idx = start + k;
        if (idx < NUM_ENT) {
            g_rowptr[idx] = run;
            g_cursor[idx] = run;
            run += g_hist[idx];
        }
    }
}

__global__ void scatter_kernel(const int* __restrict__ edge_src,
                               const int* __restrict__ edge_dst,
                               const float* __restrict__ edge_val) {
    int i = blockIdx.x * blockDim.x + threadIdx.x;
    if (i >= ETOT) return;
    int dst = edge_dst[i];
    int pos = atomicAdd(&g_cursor[dst], 1);
    int op  = i / NNZ;
    g_meta[pos] = edge_src[i] | (op << 18);
    g_eval[pos] = edge_val[i];
}

// ---------------- LSTM front-end ----------------
// grid = RANKS*2*BATCH blocks (one per (rank, dir, batch)), 256 threads.
__global__ void lstm_kernel(const int* __restrict__ queries, const float* __restrict__ emb,
                            const float* __restrict__ Wih_f, const float* __restrict__ Whh_f,
                            const float* __restrict__ bih_f, const float* __restrict__ bhh_f,
                            const float* __restrict__ Wih_b, const float* __restrict__ Whh_b,
                            const float* __restrict__ bih_b, const float* __restrict__ bhh_b)
{
    int bb  = blockIdx.x & 127;
    int dir = (blockIdx.x >> 7) & 1;
    int r   = blockIdx.x >> 8;
    const float* Wih = (dir ? Wih_b : Wih_f) + r * G4 * DIM;
    const float* Whh = (dir ? Whh_b : Whh_f) + r * G4 * HID;
    const float* bih = (dir ? bih_b : bih_f) + r * G4;
    const float* bhh = (dir ? bhh_b : bhh_f) + r * G4;

    __shared__ __align__(16) float sq[DIM];
    __shared__ __align__(16) float sh[HID];
    __shared__ float sc[HID];
    __shared__ float sz[G4];
    __shared__ float sxw[G4];

    int tid  = threadIdx.x;
    int lane = tid & 31;
    int warp = tid >> 5;   // 0..7

    if (tid < DIM) {
        int qi = queries[bb];
        sq[tid] = emb[qi * DIM + tid];
        sh[tid] = 0.f;
        sc[tid] = 0.f;
    }
    __syncthreads();

    // xw = q @ Wih^T + bih + bhh  (constant across time since x is replicated)
    {
        float4 q4 = ((const float4*)sq)[lane];
        const float4* W4 = (const float4*)Wih;
        for (int o = 0; o < 64; o++) {
            int g = warp * 64 + o;
            float4 w = W4[g * 32 + lane];
            float p = w.x * q4.x + w.y * q4.y + w.z * q4.z + w.w * q4.w;
            p = warp_sum(p);
            if (lane == 0) sxw[g] = p + bih[g] + bhh[g];
        }
    }
    __syncthreads();

    for (int t = 0; t < STEPS; t++) {
        if (t == 0) {
            for (int g = tid; g < G4; g += 256) sz[g] = sxw[g];   // h == 0
        } else {
            float4 h4 = ((const float4*)sh)[lane];
            const float4* W4 = (const float4*)Whh;
            for (int o = 0; o < 64; o++) {
                int g = warp * 64 + o;
                float4 w = W4[g * 32 + lane];
                float p = w.x * h4.x + w.y * h4.y + w.z * h4.z + w.w * h4.w;
                p = warp_sum(p);
                if (lane == 0) sz[g] = sxw[g] + p;
            }
        }
        __syncthreads();
        if (tid < HID) {
            float zi = sz[tid], zf = sz[tid + HID], zg = sz[tid + 2 * HID], zo = sz[tid + 3 * HID];
            float ig = 1.f / (1.f + expf(-zi));
            float fg = 1.f / (1.f + expf(-zf));
            float gg = tanhf(zg);
            float og = 1.f / (1.f + expf(-zo));
            float c = fg * sc[tid] + ig * gg;
            float h = og * tanhf(c);
            sc[tid] = c;
            sh[tid] = h;
            g_hseq[(((r * 2 + dir) * STEPS + t) * BATCH + bb) * HID + tid] = h;
        }
        __syncthreads();
    }
}

// grid = RANKS*STEPS (9), 128 threads (one per batch element)
__global__ void attn_kernel(const float* __restrict__ W0, const float* __restrict__ b0p) {
    int r = blockIdx.x / STEPS;
    int t = blockIdx.x % STEPS;
    __shared__ float sW[256 * 13];
    int tid = threadIdx.x;
    for (int i = tid; i < 256 * 13; i += BATCH) sW[i] = W0[i];
    __syncthreads();
    // forward state after (t+1) steps; backward state after (S-t) steps
    const float* hf = &g_hseq[(((r * 2 + 0) * STEPS + t) * BATCH + tid) * HID];
    const float* hb = &g_hseq[(((r * 2 + 1) * STEPS + (STEPS - 1 - t)) * BATCH + tid) * HID];
    float l[13];
    #pragma unroll
    for (int k = 0; k < 13; k++) l[k] = b0p[k];
    for (int d = 0; d < HID; d++) {
        float hv = hf[d];
        #pragma unroll
        for (int k = 0; k < 13; k++) l[k] += hv * sW[d * 13 + k];
    }
    for (int d = 0; d < HID; d++) {
        float hv = hb[d];
        #pragma unroll
        for (int k = 0; k < 13; k++) l[k] += hv * sW[(HID + d) * 13 + k];
    }
    float m = l[0];
    #pragma unroll
    for (int k = 1; k < 13; k++) m = fmaxf(m, l[k]);
    float s = 0.f;
    #pragma unroll
    for (int k = 0; k < 13; k++) { l[k] = expf(l[k] - m); s += l[k]; }
    float inv = 1.f / s;
    int base = ((r * STEPS + t) * 13) * BATCH + tid;
    #pragma unroll
    for (int k = 0; k < 13; k++) g_attn[base + k * BATCH] = l[k] * inv;
}

// ---------------- memory init (per rank) ----------------
__global__ void zero_flagA_kernel() {
    int i = blockIdx.x * blockDim.x + threadIdx.x;
    if (i < NUM_ENT) g_flagA[i] = 0;
}
__global__ void init_rows_kernel(const int* __restrict__ heads) {
    // zero only the head rows (all other rows are never read while unflagged)
    int row = heads[blockIdx.x];
    ((float*)g_memA)[row * BATCH + threadIdx.x] = 0.f;
}
__global__ void init_heads_kernel(const int* __restrict__ heads) {
    int b = threadIdx.x;
    int row = heads[b];
    ((float*)g_memA)[row * BATCH + b] = 1.f;
    g_flagA[row] = 1;
}

// ---------------- sparse apply: one warp per destination row ----------------
// dirflag=0: A->B (flags A->B); dirflag=1: B->A
__global__ void apply_kernel(int dirflag, int attnOff) {
    const float4*        memIn   = dirflag ? g_memB  : g_memA;
    float4*              memOut  = dirflag ? g_memA  : g_memB;
    const unsigned char* flagIn  = dirflag ? g_flagB : g_flagA;
    unsigned char*       flagOut = dirflag ? g_flagA : g_flagB;

    __shared__ __align__(16) float sAttn[13 * BATCH];
    int tid  = threadIdx.x;   // 128
    int lane = tid & 31;
    int warp = tid >> 5;
    for (int i = tid; i < 13 * BATCH; i += 128) sAttn[i] = g_attn[attnOff + i];
    __syncthreads();
    const float4* sA4 = (const float4*)sAttn;

    int j  = blockIdx.x * 4 + warp;
    int rs = g_rowptr[j];
    int re = g_rowptr[j + 1];

    float4 acc = make_float4(0.f, 0.f, 0.f, 0.f);
    int any = flagIn[j];
    if (any) {   // identity operator term
        float4 m = memIn[j * 32 + lane];
        float4 a = sA4[12 * 32 + lane];
        acc.x = a.x * m.x; acc.y = a.y * m.y; acc.z = a.z * m.z; acc.w = a.w * m.w;
    }
    for (int e = rs; e < re; e++) {
        int meta = g_meta[e];              // uniform (broadcast) load
        int src  = meta & 0x3FFFF;
        if (flagIn[src]) {                 // skip provably-zero source rows
            any = 1;
            float v  = g_eval[e];
            float4 a = sA4[(meta >> 18) * 32 + lane];
            float4 m = memIn[src * 32 + lane];
            acc.x = fmaf(v * a.x, m.x, acc.x);
            acc.y = fmaf(v * a.y, m.y, acc.y);
            acc.z = fmaf(v * a.z, m.z, acc.z);
            acc.w = fmaf(v * a.w, m.w, acc.w);
        }
    }
    memOut[j * 32 + lane] = acc;
    if (lane == 0) flagOut[j] = (unsigned char)(any ? 1 : 0);
}

// ---------------- normalize + accumulate + output ----------------
__global__ void partial_kernel() {   // grid NPART, 128 threads; reads g_memB
    int b  = threadIdx.x;
    int j0 = blockIdx.x * 200;
    const float* mem = (const float*)g_memB;
    float s = 0.f;
    for (int k = 0; k < 200; k++) s += mem[(j0 + k) * BATCH + b];
    g_part[blockIdx.x * BATCH + b] = s;
}
__global__ void norm_kernel() {      // 1 block, 128 threads
    int b = threadIdx.x;
    float s = 0.f;
    for (int k = 0; k < NPART; k++) s += g_part[k * BATCH + b];
    g_inv[b] = 1.f / fmaxf(1e-20f, s);
}
__global__ void accum_kernel(int first) {
    int i = blockIdx.x * blockDim.x + threadIdx.x;   // 5.12M
    const float* mem = (const float*)g_memB;
    float v = mem[i] * g_inv[i & 127];
    g_accum[i] = first ? v : (g_accum[i] + v);
}
__global__ void transpose_kernel(float* __restrict__ out) {
    __shared__ float tile[32][33];
    int j0 = blockIdx.x * 32, b0 = blockIdx.y * 32;
    int x = threadIdx.x, y = threadIdx.y;
    tile[y][x] = g_accum[(j0 + y) * BATCH + (b0 + x)];
    __syncthreads();
    out[(b0 + y) * NUM_ENT + (j0 + x)] = tile[x][y];
}

// ---------------- launch ----------------
extern "C" void kernel_launch(void* const* d_in, const int* in_sizes, int n_in,
                              void* d_out, int out_size) {
    const int*   queries  = (const int*)d_in[0];
    const int*   heads    = (const int*)d_in[1];
    const int*   edge_src = (const int*)d_in[2];
    const int*   edge_dst = (const int*)d_in[3];
    const float* edge_val = (const float*)d_in[4];
    const float* emb      = (const float*)d_in[5];
    const float* Wih_f    = (const float*)d_in[6];
    const float* Whh_f    = (const float*)d_in[7];
    const float* bih_f    = (const float*)d_in[8];
    const float* bhh_f    = (const float*)d_in[9];
    const float* Wih_b    = (const float*)d_in[10];
    const float* Whh_b    = (const float*)d_in[11];
    const float* bih_b    = (const float*)d_in[12];
    const float* bhh_b    = (const float*)d_in[13];
    const float* W0       = (const float*)d_in[14];
    const float* b0       = (const float*)d_in[15];
    float* out = (float*)d_out;
    (void)in_sizes; (void)n_in; (void)out_size;

    // CSR by destination (rebuilt every call; graph-static within the call)
    zero_hist_kernel<<<(NUM_ENT + 255) / 256, 256>>>();
    hist_kernel<<<(ETOT + 255) / 256, 256>>>(edge_dst);
    scan_kernel<<<1, 1024>>>();
    scatter_kernel<<<(ETOT + 255) / 256, 256>>>(edge_src, edge_dst, edge_val);

    // LSTM front-end + attention coefficients
    lstm_kernel<<<RANKS * 2 * BATCH, 256>>>(queries, emb, Wih_f, Whh_f, bih_f, bhh_f,
                                            Wih_b, Whh_b, bih_b, bhh_b);
    attn_kernel<<<RANKS * STEPS, 128>>>(W0, b0);

    for (int r = 0; r < RANKS; r++) {
        zero_flagA_kernel<<<(NUM_ENT + 255) / 256, 256>>>();
        init_rows_kernel<<<BATCH, BATCH>>>(heads);
        init_heads_kernel<<<1, BATCH>>>(heads);
        for (int t = 0; t < STEPS; t++) {
            apply_kernel<<<NUM_ENT / 4, 128>>>(t & 1, ((r * STEPS + t) * 13) * BATCH);
        }
        // result of 3 applies (A->B, B->A, A->B) lives in g_memB
        partial_kernel<<<NPART, 128>>>();
        norm_kernel<<<1, 128>>>();
        accum_kernel<<<(NUM_ENT * BATCH) / 256, 256>>>(r == 0);
    }

    transpose_kernel<<<dim3(NUM_ENT / 32, BATCH / 32), dim3(32, 32)>>>(out);
}

// round 5
// speedup vs baseline: 1.5997x; 1.5997x over previous
#include <cuda_runtime.h>
#include <math.h>

#define NUM_ENT 40000
#define NUM_EMB 24
#define NUM_OPS 12
#define DIM     128
#define HID     128
#define BATCH   128
#define NNZ     300000
#define RANKS   3
#define STEPS   3
#define ETOT    (NUM_OPS * NNZ)
#define G4      (4 * HID)
#define ROWF    (RANKS * BATCH)     // 384 floats per entity row (ranks interleaved)
#define ROW4    (ROWF / 4)          // 96 float4
#define NWORDS  (NUM_ENT / 16)      // 2500 flag words (16 bits used per uint)
#define NPART   200

// ---------------- scratch (device globals; no allocation allowed) ----------------
__device__ float        g_memA[(size_t)NUM_ENT * ROWF];   // (ENT, 3, 128)
__device__ float        g_memB[(size_t)NUM_ENT * ROWF];
__device__ int          g_hist[NUM_ENT];
__device__ int          g_rowptr[NUM_ENT + 1];
__device__ int          g_cursor[NUM_ENT];
__device__ int2         g_edge[ETOT];                     // {src | op<<18, bits(val)}
__device__ unsigned int g_bitsA[NWORDS];
__device__ unsigned int g_bitsB[NWORDS];
__device__ float        g_hseq[RANKS * 2 * STEPS * NUM_EMB * HID];
__device__ float        g_attn24[RANKS * STEPS * 13 * NUM_EMB];  // [r][t][k][q]
__device__ float        g_part[NPART * ROWF];
__device__ float        g_inv[ROWF];

// ---------------- helpers ----------------
__device__ __forceinline__ float warp_sum(float p) {
    p += __shfl_xor_sync(0xffffffffu, p, 16);
    p += __shfl_xor_sync(0xffffffffu, p, 8);
    p += __shfl_xor_sync(0xffffffffu, p, 4);
    p += __shfl_xor_sync(0xffffffffu, p, 2);
    p += __shfl_xor_sync(0xffffffffu, p, 1);
    return p;
}

// ---------------- CSR build ----------------
__global__ void zero_hist_kernel() {
    int i = blockIdx.x * blockDim.x + threadIdx.x;
    if (i < NUM_ENT) g_hist[i] = 0;
}

__global__ void hist_kernel(const int* __restrict__ edge_dst) {
    int i = blockIdx.x * blockDim.x + threadIdx.x;
    if (i < ETOT) atomicAdd(&g_hist[edge_dst[i]], 1);
}

__global__ void scan_kernel() {   // 1 block, 1024 threads
    __shared__ int spart[1024];
    int tid = threadIdx.x;
    const int CH = (NUM_ENT + 1023) / 1024;  // 40
    int start = tid * CH;
    int s = 0;
    for (int k = 0; k < CH; k++) {
        int idx = start + k;
        if (idx < NUM_ENT) s += g_hist[idx];
    }
    spart[tid] = s;
    __syncthreads();
    if (tid == 0) {
        int run = 0;
        for (int i = 0; i < 1024; i++) { int v = spart[i]; spart[i] = run; run += v; }
        g_rowptr[NUM_ENT] = run;
    }
    __syncthreads();
    int run = spart[tid];
    for (int k = 0; k < CH; k++) {
        int idx = start + k;
        if (idx < NUM_ENT) {
            g_rowptr[idx] = run;
            g_cursor[idx] = run;
            run += g_hist[idx];
        }
    }
}

__global__ void scatter_kernel(const int* __restrict__ edge_src,
                               const int* __restrict__ edge_dst,
                               const float* __restrict__ edge_val) {
    int i = blockIdx.x * blockDim.x + threadIdx.x;
    if (i >= ETOT) return;
    int dst = edge_dst[i];
    int pos = atomicAdd(&g_cursor[dst], 1);
    int op  = i / NNZ;
    g_edge[pos] = make_int2(edge_src[i] | (op << 18), __float_as_int(edge_val[i]));
}

// ---------------- LSTM front-end over the 24 distinct query embeddings ----------------
// grid = RANKS*2*NUM_EMB blocks, 256 threads.
__global__ void lstm_kernel(const float* __restrict__ emb,
                            const float* __restrict__ Wih_f, const float* __restrict__ Whh_f,
                            const float* __restrict__ bih_f, const float* __restrict__ bhh_f,
                            const float* __restrict__ Wih_b, const float* __restrict__ Whh_b,
                            const float* __restrict__ bih_b, const float* __restrict__ bhh_b)
{
    int bb  = blockIdx.x % NUM_EMB;
    int dir = (blockIdx.x / NUM_EMB) % 2;
    int r   = blockIdx.x / (2 * NUM_EMB);
    const float* Wih = (dir ? Wih_b : Wih_f) + r * G4 * DIM;
    const float* Whh = (dir ? Whh_b : Whh_f) + r * G4 * HID;
    const float* bih = (dir ? bih_b : bih_f) + r * G4;
    const float* bhh = (dir ? bhh_b : bhh_f) + r * G4;

    __shared__ __align__(16) float sq[DIM];
    __shared__ __align__(16) float sh[HID];
    __shared__ float sc[HID];
    __shared__ float sz[G4];
    __shared__ float sxw[G4];

    int tid  = threadIdx.x;
    int lane = tid & 31;
    int warp = tid >> 5;   // 0..7

    if (tid < DIM) {
        sq[tid] = emb[bb * DIM + tid];
        sh[tid] = 0.f;
        sc[tid] = 0.f;
    }
    __syncthreads();

    // xw = q @ Wih^T + bih + bhh (constant over time; x replicated)
    {
        float4 q4 = ((const float4*)sq)[lane];
        const float4* W4 = (const float4*)Wih;
        for (int o = 0; o < 64; o++) {
            int g = warp * 64 + o;
            float4 w = W4[g * 32 + lane];
            float p = w.x * q4.x + w.y * q4.y + w.z * q4.z + w.w * q4.w;
            p = warp_sum(p);
            if (lane == 0) sxw[g] = p + bih[g] + bhh[g];
        }
    }
    __syncthreads();

    for (int t = 0; t < STEPS; t++) {
        if (t == 0) {
            for (int g = tid; g < G4; g += 256) sz[g] = sxw[g];   // h == 0
        } else {
            float4 h4 = ((const float4*)sh)[lane];
            const float4* W4 = (const float4*)Whh;
            for (int o = 0; o < 64; o++) {
                int g = warp * 64 + o;
                float4 w = W4[g * 32 + lane];
                float p = w.x * h4.x + w.y * h4.y + w.z * h4.z + w.w * h4.w;
                p = warp_sum(p);
                if (lane == 0) sz[g] = sxw[g] + p;
            }
        }
        __syncthreads();
        if (tid < HID) {
            float zi = sz[tid], zf = sz[tid + HID], zg = sz[tid + 2 * HID], zo = sz[tid + 3 * HID];
            float ig = 1.f / (1.f + expf(-zi));
            float fg = 1.f / (1.f + expf(-zf));
            float gg = tanhf(zg);
            float og = 1.f / (1.f + expf(-zo));
            float c = fg * sc[tid] + ig * gg;
            float h = og * tanhf(c);
            sc[tid] = c;
            sh[tid] = h;
            g_hseq[(((r * 2 + dir) * STEPS + t) * NUM_EMB + bb) * HID + tid] = h;
        }
        __syncthreads();
    }
}

// grid = RANKS*STEPS (9) blocks, 32 threads (one per distinct query, 24 used)
__global__ void attn_kernel(const float* __restrict__ W0, const float* __restrict__ b0p) {
    int r = blockIdx.x / STEPS;
    int t = blockIdx.x % STEPS;
    __shared__ float sW[256 * 13];
    int tid = threadIdx.x;
    for (int i = tid; i < 256 * 13; i += 32) sW[i] = W0[i];
    __syncthreads();
    if (tid >= NUM_EMB) return;
    int q = tid;
    const float* hf = &g_hseq[(((r * 2 + 0) * STEPS + t) * NUM_EMB + q) * HID];
    const float* hb = &g_hseq[(((r * 2 + 1) * STEPS + (STEPS - 1 - t)) * NUM_EMB + q) * HID];
    float l[13];
    #pragma unroll
    for (int k = 0; k < 13; k++) l[k] = b0p[k];
    for (int d = 0; d < HID; d++) {
        float hv = hf[d];
        #pragma unroll
        for (int k = 0; k < 13; k++) l[k] += hv * sW[d * 13 + k];
    }
    for (int d = 0; d < HID; d++) {
        float hv = hb[d];
        #pragma unroll
        for (int k = 0; k < 13; k++) l[k] += hv * sW[(HID + d) * 13 + k];
    }
    float m = l[0];
    #pragma unroll
    for (int k = 1; k < 13; k++) m = fmaxf(m, l[k]);
    float s = 0.f;
    #pragma unroll
    for (int k = 0; k < 13; k++) { l[k] = expf(l[k] - m); s += l[k]; }
    float inv = 1.f / s;
    #pragma unroll
    for (int k = 0; k < 13; k++)
        g_attn24[((r * STEPS + t) * 13 + k) * NUM_EMB + q] = l[k] * inv;
}

// ---------------- memory / flag init (once; flags identical across ranks) ----------------
__global__ void zero_bits_kernel() {
    int i = blockIdx.x * blockDim.x + threadIdx.x;
    if (i < NWORDS) g_bitsA[i] = 0;
}
__global__ void init_rows_kernel(const int* __restrict__ heads) {
    int row = heads[blockIdx.x];
    g_memA[(size_t)row * ROWF + threadIdx.x] = 0.f;   // 384 threads
}
__global__ void init_set_kernel(const int* __restrict__ heads) {
    int b = threadIdx.x;     // 128
    int row = heads[b];
    #pragma unroll
    for (int r = 0; r < RANKS; r++)
        g_memA[(size_t)row * ROWF + r * BATCH + b] = 1.f;
    atomicOr(&g_bitsA[row >> 4], 1u << (row & 15));
}

// ---------------- fused sparse apply: 3 ranks, one warp per destination row ----------------
// grid = NUM_ENT/16 = 2500 blocks, 512 threads (16 warps). Block b owns rows [16b, 16b+16)
// and therefore exactly flag word b (plain store, no atomics, no pre-zero).
__global__ void apply_kernel(int dirflag, int t, const int* __restrict__ queries) {
    __shared__ __align__(16) float4 sAttn4[RANKS * 13 * 32];  // [(r*13+k)*32 + lane] over batch
    __shared__ unsigned int sbits[NWORDS];
    __shared__ int sq[BATCH];
    __shared__ unsigned char sAny[16];

    const float4* memIn4  = (const float4*)(dirflag ? g_memB : g_memA);
    float4*       memOut4 = (float4*)(dirflag ? g_memA : g_memB);
    const unsigned int* bitsIn  = dirflag ? g_bitsB : g_bitsA;
    unsigned int*       bitsOut = dirflag ? g_bitsA : g_bitsB;

    int tid = threadIdx.x;
    for (int i = tid; i < BATCH; i += 512) sq[i] = queries[i];
    for (int i = tid; i < NWORDS; i += 512) sbits[i] = bitsIn[i];
    __syncthreads();
    float* sAttnF = (float*)sAttn4;
    for (int i = tid; i < RANKS * 13 * BATCH; i += 512) {
        int rk = i >> 7;           // r*13 + k
        int b  = i & 127;
        int r  = rk / 13, k = rk - r * 13;
        sAttnF[i] = g_attn24[((r * STEPS + t) * 13 + k) * NUM_EMB + sq[b]];
    }
    __syncthreads();

    int lane = tid & 31;
    int warp = tid >> 5;
    int j = blockIdx.x * 16 + warp;

    int rs = g_rowptr[j];
    int re = g_rowptr[j + 1];

    float4 acc[RANKS];
    #pragma unroll
    for (int r = 0; r < RANKS; r++) acc[r] = make_float4(0.f, 0.f, 0.f, 0.f);

    unsigned int any = (sbits[j >> 4] >> (j & 15)) & 1u;
    if (any) {   // identity operator (k=12)
        const float4* mrow = memIn4 + (size_t)j * ROW4;
        #pragma unroll
        for (int r = 0; r < RANKS; r++) {
            float4 a = sAttn4[(r * 13 + 12) * 32 + lane];
            float4 m = mrow[r * 32 + lane];
            acc[r].x = a.x * m.x; acc[r].y = a.y * m.y;
            acc[r].z = a.z * m.z; acc[r].w = a.w * m.w;
        }
    }

    for (int e0 = rs; e0 < re; e0 += 32) {
        int e = e0 + lane;
        int meta = 0; float val = 0.f;
        bool act = false;
        if (e < re) {
            int2 ev = g_edge[e];                 // coalesced 8B
            meta = ev.x;
            val  = __int_as_float(ev.y);
            int s = meta & 0x3FFFF;
            act = (sbits[s >> 4] >> (s & 15)) & 1u;
        }
        unsigned int mask = __ballot_sync(0xffffffffu, act);
        any |= mask;
        while (mask) {
            int k = __ffs(mask) - 1;
            mask &= mask - 1;
            int   mk = __shfl_sync(0xffffffffu, meta, k);
            float vk = __shfl_sync(0xffffffffu, val,  k);
            int srck = mk & 0x3FFFF;
            int opk  = mk >> 18;
            const float4* mrow = memIn4 + (size_t)srck * ROW4;
            #pragma unroll
            for (int r = 0; r < RANKS; r++) {
                float4 m = mrow[r * 32 + lane];
                float4 a = sAttn4[(r * 13 + opk) * 32 + lane];
                acc[r].x = fmaf(vk * a.x, m.x, acc[r].x);
                acc[r].y = fmaf(vk * a.y, m.y, acc[r].y);
                acc[r].z = fmaf(vk * a.z, m.z, acc[r].z);
                acc[r].w = fmaf(vk * a.w, m.w, acc[r].w);
            }
        }
    }

    float4* orow = memOut4 + (size_t)j * ROW4;
    #pragma unroll
    for (int r = 0; r < RANKS; r++) orow[r * 32 + lane] = acc[r];

    if (lane == 0) sAny[warp] = any ? 1 : 0;
    __syncthreads();
    if (tid < 32) {
        unsigned int m = __ballot_sync(0xffffffffu, tid < 16 && sAny[tid]);
        if (tid == 0) bitsOut[blockIdx.x] = m & 0xFFFFu;
    }
}

// ---------------- normalize + fused output ----------------
__global__ void partial_kernel() {   // grid NPART, 384 threads; reads g_memB (final state)
    int tid = threadIdx.x;
    int j0  = blockIdx.x * (NUM_ENT / NPART);
    float s = 0.f;
    for (int k = 0; k < NUM_ENT / NPART; k++)
        s += g_memB[(size_t)(j0 + k) * ROWF + tid];
    g_part[blockIdx.x * ROWF + tid] = s;
}
__global__ void norm_kernel() {      // 1 block, 384 threads
    int tid = threadIdx.x;
    float s = 0.f;
    for (int k = 0; k < NPART; k++) s += g_part[k * ROWF + tid];
    g_inv[tid] = 1.f / fmaxf(1e-20f, s);
}
// out[b][j] = sum_r memB[j][r][b] * inv[r][b]; tiled transpose
__global__ void final_kernel(float* __restrict__ out) {
    __shared__ float tile[32][33];
    __shared__ float sinv[RANKS][32];
    int j0 = blockIdx.x * 32, b0 = blockIdx.y * 32;
    int x = threadIdx.x, y = threadIdx.y;
    if (y < RANKS) sinv[y][x] = g_inv[y * BATCH + b0 + x];
    __syncthreads();
    const float* row = &g_memB[(size_t)(j0 + y) * ROWF + b0 + x];
    float v = row[0] * sinv[0][x] + row[BATCH] * sinv[1][x] + row[2 * BATCH] * sinv[2][x];
    tile[y][x] = v;
    __syncthreads();
    out[(size_t)(b0 + y) * NUM_ENT + (j0 + x)] = tile[x][y];
}

// ---------------- launch ----------------
extern "C" void kernel_launch(void* const* d_in, const int* in_sizes, int n_in,
                              void* d_out, int out_size) {
    const int*   queries  = (const int*)d_in[0];
    const int*   heads    = (const int*)d_in[1];
    const int*   edge_src = (const int*)d_in[2];
    const int*   edge_dst = (const int*)d_in[3];
    const float* edge_val = (const float*)d_in[4];
    const float* emb      = (const float*)d_in[5];
    const float* Wih_f    = (const float*)d_in[6];
    const float* Whh_f    = (const float*)d_in[7];
    const float* bih_f    = (const float*)d_in[8];
    const float* bhh_f    = (const float*)d_in[9];
    const float* Wih_b    = (const float*)d_in[10];
    const float* Whh_b    = (const float*)d_in[11];
    const float* bih_b    = (const float*)d_in[12];
    const float* bhh_b    = (const float*)d_in[13];
    const float* W0       = (const float*)d_in[14];
    const float* b0       = (const float*)d_in[15];
    float* out = (float*)d_out;
    (void)in_sizes; (void)n_in; (void)out_size;

    // CSR by destination
    zero_hist_kernel<<<(NUM_ENT + 255) / 256, 256>>>();
    hist_kernel<<<(ETOT + 255) / 256, 256>>>(edge_dst);
    scan_kernel<<<1, 1024>>>();
    scatter_kernel<<<(ETOT + 255) / 256, 256>>>(edge_src, edge_dst, edge_val);

    // LSTM + attention over the 24 distinct query embeddings
    lstm_kernel<<<RANKS * 2 * NUM_EMB, 256>>>(emb, Wih_f, Whh_f, bih_f, bhh_f,
                                              Wih_b, Whh_b, bih_b, bhh_b);
    attn_kernel<<<RANKS * STEPS, 32>>>(W0, b0);

    // init state + flags (shared across ranks)
    zero_bits_kernel<<<(NWORDS + 255) / 256, 256>>>();
    init_rows_kernel<<<BATCH, ROWF>>>(heads);
    init_set_kernel<<<1, BATCH>>>(heads);

    // 3 fused applies (all ranks per launch): A->B, B->A, A->B
    for (int t = 0; t < STEPS; t++)
        apply_kernel<<<NUM_ENT / 16, 512>>>(t & 1, t, queries);

    // normalize per rank, sum ranks, transpose to (B, ENT)
    partial_kernel<<<NPART, ROWF>>>();
    norm_kernel<<<1, ROWF>>>();
    final_kernel<<<dim3(NUM_ENT / 32, BATCH / 32), dim3(32, 32)>>>(out);
}

// round 6
// speedup vs baseline: 2.4985x; 1.5619x over previous
#include <cuda_runtime.h>
#include <cuda_fp16.h>
#include <math.h>

#define NUM_ENT 40000
#define NUM_EMB 24
#define NUM_OPS 12
#define DIM     128
#define HID     128
#define BATCH   128
#define NNZ     300000
#define RANKS   3
#define STEPS   3
#define ETOT    (NUM_OPS * NNZ)
#define G4      (4 * HID)
#define ROWF    (RANKS * BATCH)     // 384 floats per entity row (ranks interleaved)
#define ROW4    (ROWF / 4)          // 96 float4 (fp32 rows)
#define ROWH2   (ROWF / 4)          // 96 uint2  (fp16 rows: 4 halves per uint2)
#define NWORDS  (NUM_ENT / 16)      // 2500 flag words (16 bits used per uint)
#define NPART   200

// ---------------- scratch (device globals; no allocation allowed) ----------------
__device__ float        g_memF[(size_t)NUM_ENT * ROWF];   // fp32: init (t0 in) + final (t2 out)
__device__ uint2        g_memH1[(size_t)NUM_ENT * ROWH2]; // fp16 state after t=0
__device__ uint2        g_memH2[(size_t)NUM_ENT * ROWH2]; // fp16 state after t=1
__device__ int          g_hist[NUM_ENT];
__device__ int          g_rowptr[NUM_ENT + 1];
__device__ int          g_cursor[NUM_ENT];
__device__ int2         g_edge[ETOT];                     // {src | op<<18, bits(val)}
__device__ unsigned int g_bitsA[NWORDS];
__device__ unsigned int g_bitsB[NWORDS];
__device__ float        g_hseq[RANKS * 2 * STEPS * NUM_EMB * HID];
__device__ float        g_attn24[RANKS * STEPS * 13 * NUM_EMB];  // [r][t][k][q]
__device__ float        g_part[NPART * ROWF];
__device__ float        g_inv[ROWF];

// ---------------- helpers ----------------
__device__ __forceinline__ float warp_sum(float p) {
    p += __shfl_xor_sync(0xffffffffu, p, 16);
    p += __shfl_xor_sync(0xffffffffu, p, 8);
    p += __shfl_xor_sync(0xffffffffu, p, 4);
    p += __shfl_xor_sync(0xffffffffu, p, 2);
    p += __shfl_xor_sync(0xffffffffu, p, 1);
    return p;
}

// ---------------- CSR build ----------------
__global__ void zero_misc_kernel() {
    int i = blockIdx.x * blockDim.x + threadIdx.x;
    if (i < NUM_ENT) g_hist[i] = 0;
    if (i < NWORDS)  g_bitsA[i] = 0;
}

__global__ void hist_kernel(const int4* __restrict__ edge_dst4) {
    int i = blockIdx.x * blockDim.x + threadIdx.x;
    if (i < ETOT / 4) {
        int4 d = edge_dst4[i];
        atomicAdd(&g_hist[d.x], 1);
        atomicAdd(&g_hist[d.y], 1);
        atomicAdd(&g_hist[d.z], 1);
        atomicAdd(&g_hist[d.w], 1);
    }
}

__global__ void scan_kernel() {   // 1 block, 1024 threads
    __shared__ int spart[1024];
    int tid = threadIdx.x;
    const int CH = (NUM_ENT + 1023) / 1024;  // 40
    int start = tid * CH;
    int s = 0;
    for (int k = 0; k < CH; k++) {
        int idx = start + k;
        if (idx < NUM_ENT) s += g_hist[idx];
    }
    spart[tid] = s;
    __syncthreads();
    if (tid == 0) {
        int run = 0;
        for (int i = 0; i < 1024; i++) { int v = spart[i]; spart[i] = run; run += v; }
        g_rowptr[NUM_ENT] = run;
    }
    __syncthreads();
    int run = spart[tid];
    for (int k = 0; k < CH; k++) {
        int idx = start + k;
        if (idx < NUM_ENT) {
            g_rowptr[idx] = run;
            g_cursor[idx] = run;
            run += g_hist[idx];
        }
    }
}

__global__ void scatter_kernel(const int* __restrict__ edge_src,
                               const int* __restrict__ edge_dst,
                               const float* __restrict__ edge_val) {
    int i = blockIdx.x * blockDim.x + threadIdx.x;
    if (i >= ETOT) return;
    int dst = edge_dst[i];
    int pos = atomicAdd(&g_cursor[dst], 1);
    int op  = i / NNZ;
    g_edge[pos] = make_int2(edge_src[i] | (op << 18), __float_as_int(edge_val[i]));
}

// ---------------- LSTM front-end over the 24 distinct query embeddings ----------------
__global__ void lstm_kernel(const float* __restrict__ emb,
                            const float* __restrict__ Wih_f, const float* __restrict__ Whh_f,
                            const float* __restrict__ bih_f, const float* __restrict__ bhh_f,
                            const float* __restrict__ Wih_b, const float* __restrict__ Whh_b,
                            const float* __restrict__ bih_b, const float* __restrict__ bhh_b)
{
    int bb  = blockIdx.x % NUM_EMB;
    int dir = (blockIdx.x / NUM_EMB) % 2;
    int r   = blockIdx.x / (2 * NUM_EMB);
    const float* Wih = (dir ? Wih_b : Wih_f) + r * G4 * DIM;
    const float* Whh = (dir ? Whh_b : Whh_f) + r * G4 * HID;
    const float* bih = (dir ? bih_b : bih_f) + r * G4;
    const float* bhh = (dir ? bhh_b : bhh_f) + r * G4;

    __shared__ __align__(16) float sq[DIM];
    __shared__ __align__(16) float sh[HID];
    __shared__ float sc[HID];
    __shared__ float sz[G4];
    __shared__ float sxw[G4];

    int tid  = threadIdx.x;
    int lane = tid & 31;
    int warp = tid >> 5;

    if (tid < DIM) {
        sq[tid] = emb[bb * DIM + tid];
        sh[tid] = 0.f;
        sc[tid] = 0.f;
    }
    __syncthreads();

    {
        float4 q4 = ((const float4*)sq)[lane];
        const float4* W4 = (const float4*)Wih;
        for (int o = 0; o < 64; o++) {
            int g = warp * 64 + o;
            float4 w = W4[g * 32 + lane];
            float p = w.x * q4.x + w.y * q4.y + w.z * q4.z + w.w * q4.w;
            p = warp_sum(p);
            if (lane == 0) sxw[g] = p + bih[g] + bhh[g];
        }
    }
    __syncthreads();

    for (int t = 0; t < STEPS; t++) {
        if (t == 0) {
            for (int g = tid; g < G4; g += 256) sz[g] = sxw[g];
        } else {
            float4 h4 = ((const float4*)sh)[lane];
            const float4* W4 = (const float4*)Whh;
            for (int o = 0; o < 64; o++) {
                int g = warp * 64 + o;
                float4 w = W4[g * 32 + lane];
                float p = w.x * h4.x + w.y * h4.y + w.z * h4.z + w.w * h4.w;
                p = warp_sum(p);
                if (lane == 0) sz[g] = sxw[g] + p;
            }
        }
        __syncthreads();
        if (tid < HID) {
            float zi = sz[tid], zf = sz[tid + HID], zg = sz[tid + 2 * HID], zo = sz[tid + 3 * HID];
            float ig = 1.f / (1.f + expf(-zi));
            float fg = 1.f / (1.f + expf(-zf));
            float gg = tanhf(zg);
            float og = 1.f / (1.f + expf(-zo));
            float c = fg * sc[tid] + ig * gg;
            float h = og * tanhf(c);
            sc[tid] = c;
            sh[tid] = h;
            g_hseq[(((r * 2 + dir) * STEPS + t) * NUM_EMB + bb) * HID + tid] = h;
        }
        __syncthreads();
    }
}

// grid = RANKS*STEPS (9) blocks, 32 threads
__global__ void attn_kernel(const float* __restrict__ W0, const float* __restrict__ b0p) {
    int r = blockIdx.x / STEPS;
    int t = blockIdx.x % STEPS;
    __shared__ float sW[256 * 13];
    int tid = threadIdx.x;
    for (int i = tid; i < 256 * 13; i += 32) sW[i] = W0[i];
    __syncthreads();
    if (tid >= NUM_EMB) return;
    int q = tid;
    const float* hf = &g_hseq[(((r * 2 + 0) * STEPS + t) * NUM_EMB + q) * HID];
    const float* hb = &g_hseq[(((r * 2 + 1) * STEPS + (STEPS - 1 - t)) * NUM_EMB + q) * HID];
    float l[13];
    #pragma unroll
    for (int k = 0; k < 13; k++) l[k] = b0p[k];
    for (int d = 0; d < HID; d++) {
        float hv = hf[d];
        #pragma unroll
        for (int k = 0; k < 13; k++) l[k] += hv * sW[d * 13 + k];
    }
    for (int d = 0; d < HID; d++) {
        float hv = hb[d];
        #pragma unroll
        for (int k = 0; k < 13; k++) l[k] += hv * sW[(HID + d) * 13 + k];
    }
    float m = l[0];
    #pragma unroll
    for (int k = 1; k < 13; k++) m = fmaxf(m, l[k]);
    float s = 0.f;
    #pragma unroll
    for (int k = 0; k < 13; k++) { l[k] = expf(l[k] - m); s += l[k]; }
    float inv = 1.f / s;
    #pragma unroll
    for (int k = 0; k < 13; k++)
        g_attn24[((r * STEPS + t) * 13 + k) * NUM_EMB + q] = l[k] * inv;
}

// ---------------- memory / flag init ----------------
__global__ void init_rows_kernel(const int* __restrict__ heads) {
    int row = heads[blockIdx.x];
    g_memF[(size_t)row * ROWF + threadIdx.x] = 0.f;   // 384 threads
}
__global__ void init_set_kernel(const int* __restrict__ heads) {
    int b = threadIdx.x;     // 128
    int row = heads[b];
    #pragma unroll
    for (int r = 0; r < RANKS; r++)
        g_memF[(size_t)row * ROWF + r * BATCH + b] = 1.f;
    atomicOr(&g_bitsA[row >> 4], 1u << (row & 15));
}

// ---------------- fused sparse apply (3 ranks), templated per step ----------------
// STEP 0: fp32 g_memF  -> fp16 g_memH1, bitsA -> bitsB
// STEP 1: fp16 g_memH1 -> fp16 g_memH2, bitsB -> bitsA
// STEP 2: fp16 g_memH2 -> fp32 g_memF,  bitsA -> (none)
// grid = NUM_ENT/16 = 2500 blocks, 512 threads (16 warps); block b owns flag word b.
template<int STEP>
__global__ void apply_kernel(const int* __restrict__ queries) {
    constexpr bool IN_HALF     = (STEP >= 1);
    constexpr bool OUT_HALF    = (STEP <= 1);
    constexpr bool WRITE_FLAGS = (STEP < 2);

    __shared__ __align__(16) float4 sAttn4[RANKS * 13 * 32];
    __shared__ unsigned int sbits[NWORDS];
    __shared__ int sq[BATCH];
    __shared__ unsigned char sAny[16];

    const unsigned int* bitsIn  = (STEP == 1) ? g_bitsB : g_bitsA;
    unsigned int*       bitsOut = (STEP == 0) ? g_bitsB : g_bitsA;

    int tid = threadIdx.x;
    for (int i = tid; i < BATCH; i += 512) sq[i] = queries[i];
    for (int i = tid; i < NWORDS; i += 512) sbits[i] = bitsIn[i];
    __syncthreads();
    float* sAttnF = (float*)sAttn4;
    for (int i = tid; i < RANKS * 13 * BATCH; i += 512) {
        int rk = i >> 7;
        int b  = i & 127;
        int r  = rk / 13, k = rk - r * 13;
        sAttnF[i] = g_attn24[((r * STEPS + STEP) * 13 + k) * NUM_EMB + sq[b]];
    }
    __syncthreads();

    int lane = tid & 31;
    int warp = tid >> 5;
    int j = blockIdx.x * 16 + warp;

    int rs = g_rowptr[j];
    int re = g_rowptr[j + 1];

    float4 acc[RANKS];
    #pragma unroll
    for (int r = 0; r < RANKS; r++) acc[r] = make_float4(0.f, 0.f, 0.f, 0.f);

    unsigned int any = (sbits[j >> 4] >> (j & 15)) & 1u;
    if (any) {   // identity operator (k=12)
        #pragma unroll
        for (int r = 0; r < RANKS; r++) {
            float4 a = sAttn4[(r * 13 + 12) * 32 + lane];
            float4 m;
            if constexpr (IN_HALF) {
                uint2 u = ((const uint2*)(STEP == 1 ? g_memH1 : g_memH2))[(size_t)j * ROWH2 + r * 32 + lane];
                float2 f0 = __half22float2(*reinterpret_cast<__half2*>(&u.x));
                float2 f1 = __half22float2(*reinterpret_cast<__half2*>(&u.y));
                m = make_float4(f0.x, f0.y, f1.x, f1.y);
            } else {
                m = ((const float4*)g_memF)[(size_t)j * ROW4 + r * 32 + lane];
            }
            acc[r].x = a.x * m.x; acc[r].y = a.y * m.y;
            acc[r].z = a.z * m.z; acc[r].w = a.w * m.w;
        }
    }

    for (int e0 = rs; e0 < re; e0 += 32) {
        int e = e0 + lane;
        int meta = 0; float val = 0.f;
        bool act = false;
        if (e < re) {
            int2 ev = g_edge[e];
            meta = ev.x;
            val  = __int_as_float(ev.y);
            int s = meta & 0x3FFFF;
            act = (sbits[s >> 4] >> (s & 15)) & 1u;
        }
        unsigned int mask = __ballot_sync(0xffffffffu, act);
        any |= mask;
        while (mask) {
            int k = __ffs(mask) - 1;
            mask &= mask - 1;
            int   mk = __shfl_sync(0xffffffffu, meta, k);
            float vk = __shfl_sync(0xffffffffu, val,  k);
            int srck = mk & 0x3FFFF;
            int opk  = mk >> 18;
            if constexpr (IN_HALF) {
                const uint2* mrow = ((const uint2*)(STEP == 1 ? g_memH1 : g_memH2)) + (size_t)srck * ROWH2;
                #pragma unroll
                for (int r = 0; r < RANKS; r++) {
                    uint2 u = mrow[r * 32 + lane];
                    float2 f0 = __half22float2(*reinterpret_cast<__half2*>(&u.x));
                    float2 f1 = __half22float2(*reinterpret_cast<__half2*>(&u.y));
                    float4 a = sAttn4[(r * 13 + opk) * 32 + lane];
                    acc[r].x = fmaf(vk * a.x, f0.x, acc[r].x);
                    acc[r].y = fmaf(vk * a.y, f0.y, acc[r].y);
                    acc[r].z = fmaf(vk * a.z, f1.x, acc[r].z);
                    acc[r].w = fmaf(vk * a.w, f1.y, acc[r].w);
                }
            } else {
                const float4* mrow = ((const float4*)g_memF) + (size_t)srck * ROW4;
                #pragma unroll
                for (int r = 0; r < RANKS; r++) {
                    float4 m = mrow[r * 32 + lane];
                    float4 a = sAttn4[(r * 13 + opk) * 32 + lane];
                    acc[r].x = fmaf(vk * a.x, m.x, acc[r].x);
                    acc[r].y = fmaf(vk * a.y, m.y, acc[r].y);
                    acc[r].z = fmaf(vk * a.z, m.z, acc[r].z);
                    acc[r].w = fmaf(vk * a.w, m.w, acc[r].w);
                }
            }
        }
    }

    if constexpr (OUT_HALF) {
        uint2* orow = ((uint2*)(STEP == 0 ? g_memH1 : g_memH2)) + (size_t)j * ROWH2;
        #pragma unroll
        for (int r = 0; r < RANKS; r++) {
            __half2 h0 = __floats2half2_rn(acc[r].x, acc[r].y);
            __half2 h1 = __floats2half2_rn(acc[r].z, acc[r].w);
            uint2 o;
            o.x = *reinterpret_cast<unsigned int*>(&h0);
            o.y = *reinterpret_cast<unsigned int*>(&h1);
            orow[r * 32 + lane] = o;
        }
    } else {
        float4* orow = ((float4*)g_memF) + (size_t)j * ROW4;
        #pragma unroll
        for (int r = 0; r < RANKS; r++) orow[r * 32 + lane] = acc[r];
    }

    if constexpr (WRITE_FLAGS) {
        if (lane == 0) sAny[warp] = any ? 1 : 0;
        __syncthreads();
        if (tid < 32) {
            unsigned int m = __ballot_sync(0xffffffffu, tid < 16 && sAny[tid]);
            if (tid == 0) bitsOut[blockIdx.x] = m & 0xFFFFu;
        }
    }
}

// ---------------- normalize + fused output ----------------
__global__ void partial_kernel() {   // grid NPART, 384 threads; reads g_memF (final state)
    int tid = threadIdx.x;
    int j0  = blockIdx.x * (NUM_ENT / NPART);
    float s = 0.f;
    for (int k = 0; k < NUM_ENT / NPART; k++)
        s += g_memF[(size_t)(j0 + k) * ROWF + tid];
    g_part[blockIdx.x * ROWF + tid] = s;
}
__global__ void norm_kernel() {      // 1 block, 384 threads
    int tid = threadIdx.x;
    float s = 0.f;
    for (int k = 0; k < NPART; k++) s += g_part[k * ROWF + tid];
    g_inv[tid] = 1.f / fmaxf(1e-20f, s);
}
__global__ void final_kernel(float* __restrict__ out) {
    __shared__ float tile[32][33];
    __shared__ float sinv[RANKS][32];
    int j0 = blockIdx.x * 32, b0 = blockIdx.y * 32;
    int x = threadIdx.x, y = threadIdx.y;
    if (y < RANKS) sinv[y][x] = g_inv[y * BATCH + b0 + x];
    __syncthreads();
    const float* row = &g_memF[(size_t)(j0 + y) * ROWF + b0 + x];
    float v = row[0] * sinv[0][x] + row[BATCH] * sinv[1][x] + row[2 * BATCH] * sinv[2][x];
    tile[y][x] = v;
    __syncthreads();
    out[(size_t)(b0 + y) * NUM_ENT + (j0 + x)] = tile[x][y];
}

// ---------------- launch ----------------
extern "C" void kernel_launch(void* const* d_in, const int* in_sizes, int n_in,
                              void* d_out, int out_size) {
    const int*   queries  = (const int*)d_in[0];
    const int*   heads    = (const int*)d_in[1];
    const int*   edge_src = (const int*)d_in[2];
    const int*   edge_dst = (const int*)d_in[3];
    const float* edge_val = (const float*)d_in[4];
    const float* emb      = (const float*)d_in[5];
    const float* Wih_f    = (const float*)d_in[6];
    const float* Whh_f    = (const float*)d_in[7];
    const float* bih_f    = (const float*)d_in[8];
    const float* bhh_f    = (const float*)d_in[9];
    const float* Wih_b    = (const float*)d_in[10];
    const float* Whh_b    = (const float*)d_in[11];
    const float* bih_b    = (const float*)d_in[12];
    const float* bhh_b    = (const float*)d_in[13];
    const float* W0       = (const float*)d_in[14];
    const float* b0       = (const float*)d_in[15];
    float* out = (float*)d_out;
    (void)in_sizes; (void)n_in; (void)out_size;

    // CSR by destination + flag init
    zero_misc_kernel<<<(NUM_ENT + 255) / 256, 256>>>();
    hist_kernel<<<(ETOT / 4 + 255) / 256, 256>>>((const int4*)edge_dst);
    scan_kernel<<<1, 1024>>>();
    scatter_kernel<<<(ETOT + 255) / 256, 256>>>(edge_src, edge_dst, edge_val);

    // LSTM + attention over the 24 distinct query embeddings
    lstm_kernel<<<RANKS * 2 * NUM_EMB, 256>>>(emb, Wih_f, Whh_f, bih_f, bhh_f,
                                              Wih_b, Whh_b, bih_b, bhh_b);
    attn_kernel<<<RANKS * STEPS, 32>>>(W0, b0);

    // init state + flags (shared across ranks)
    init_rows_kernel<<<BATCH, ROWF>>>(heads);
    init_set_kernel<<<1, BATCH>>>(heads);

    // 3 fused applies: fp32 -> fp16 -> fp16 -> fp32
    apply_kernel<0><<<NUM_ENT / 16, 512>>>(queries);
    apply_kernel<1><<<NUM_ENT / 16, 512>>>(queries);
    apply_kernel<2><<<NUM_ENT / 16, 512>>>(queries);

    // normalize per rank, sum ranks, transpose to (B, ENT)
    partial_kernel<<<NPART, ROWF>>>();
    norm_kernel<<<1, ROWF>>>();
    final_kernel<<<dim3(NUM_ENT / 32, BATCH / 32), dim3(32, 32)>>>(out);
}